// round 3
// baseline (speedup 1.0000x reference)
#include <cuda_runtime.h>

// CRF forward recursion, exp2-domain with lagged renormalization.
// CTA = 256 threads = 8 warps, TWO batches: warps 0-3 -> batch A, warps 4-7
// -> batch B. SMSP = wid%4, so every scheduler holds one warp of each batch:
// two independent per-step dependency chains hide each other's latency.
// Per batch: warp w4 owns nxt-columns [16*w4, 16*w4+16); lanes l and l+16
// split the 64-long prev reduction, combined by one butterfly shuffle.
// p = exp2(alpha) lives in per-batch double-buffered smem. One NAMED barrier
// (128 threads) per batch per timestep.

#define FULLMASK 0xffffffffu

__device__ __forceinline__ float ex2f_(float x) {
    float r; asm("ex2.approx.f32 %0, %1;" : "=f"(r) : "f"(x)); return r;
}
__device__ __forceinline__ float lg2f_(float x) {
    float r; asm("lg2.approx.f32 %0, %1;" : "=f"(r) : "f"(x)); return r;
}

// padded p index: halves start at 0 and 36 (both 16B-aligned)
__device__ __forceinline__ int pidx(int i) { return i + ((i >> 5) << 2); }

__global__ __launch_bounds__(256, 1)
void crf_forward_kernel(const float* __restrict__ X,
                        const float* __restrict__ trans,
                        float* __restrict__ out,
                        int B, int T)
{
    constexpr float LOG2E = 1.4426950408889634f;
    constexpr float LN2   = 0.6931471805599453f;
    constexpr float NEG2  = -10000.0f * 1.4426950408889634f;

    const int tid  = threadIdx.x;
    const int wid  = tid >> 5;
    const int g    = wid >> 2;                 // batch slot in CTA: 0/1
    const int w4   = wid & 3;                  // warp within batch
    const int lane = tid & 31;
    const int col  = (w4 << 4) | (lane & 15);  // owned nxt column
    const int half = lane >> 4;                // prev half

    int b = blockIdx.x * 2 + g;
    if (b >= B) b = blockIdx.x * 2;            // defensive (B even here)

    // [batch][double-buffer][padded 64 floats]
    __shared__ __align__(16) float pbuf[2][2][72];
    __shared__ float dslot[2][2];              // [batch][buffer]

    // E2 slice: 32 prev rows (this half) for this column, in registers.
    // Column 0 (tag 'B') overridden to 1.0; -1e4 re-applied after the log.
    float e[32];
#pragma unroll
    for (int j = 0; j < 32; j++) {
        const float tv = trans[(half * 32 + j) * 64 + col];
        e[j] = (col == 0) ? 1.0f : ex2f_(tv * LOG2E);
    }

    // init p = (1, 0, ..., 0)
    if (lane < 16)
        pbuf[g][0][pidx(col)] = (col == 0) ? 1.0f : 0.0f;
    if (tid == 0) { dslot[0][0] = 0.0f; dslot[1][0] = 0.0f; }

    const float* __restrict__ xp = X + (size_t)b * T * 64 + col;
    float x = xp[0];
    float M = 0.f, a = 0.f;

    __syncthreads();

    const int pbase = pidx(half * 32);         // 0 or 36
    const int barid = 1 + g;

    for (int t = 0; t < T; t++) {
        const int cur = t & 1;

        const float d = dslot[g][cur];         // lagged shift (broadcast LDS)

        // prefetch next emission (overlaps whole step; uniform branch)
        float nx = 0.f;
        if (t + 1 < T) nx = xp[64];
        xp += 64;

        // half-matvec: 32 prev values from smem, E2 in registers
        float s0 = 0.f, s1 = 0.f, s2 = 0.f, s3 = 0.f;
#pragma unroll
        for (int k = 0; k < 8; k++) {
            const float4 p = *(const float4*)&pbuf[g][cur][pbase + 4 * k];
            s0 = fmaf(p.x, e[4 * k + 0], s0);
            s1 = fmaf(p.y, e[4 * k + 1], s1);
            s2 = fmaf(p.z, e[4 * k + 2], s2);
            s3 = fmaf(p.w, e[4 * k + 3], s3);
        }
        float S = (s0 + s1) + (s2 + s3);
        S += __shfl_xor_sync(FULLMASK, S, 16); // combine prev halves

        // log, emission, mask, re-shift, exp
        float r = fmaf(x, LOG2E, lg2f_(S));
        if (col == 0) r += NEG2;

        a = r - d;
        M += d;
        const float pn = ex2f_(a);

        if (lane < 16)
            pbuf[g][cur ^ 1][pidx(col)] = pn;
        if (w4 == 0 && lane == 2)              // col==2 -> next step's shift
            dslot[g][cur ^ 1] = a;

        x = nx;
        asm volatile("bar.sync %0, 128;" :: "r"(barid) : "memory");
    }

    if (lane < 16)
        out[(size_t)b * 64 + col] = (a + M) * LN2;
}

extern "C" void kernel_launch(void* const* d_in, const int* in_sizes, int n_in,
                              void* d_out, int out_size)
{
    const float* X     = (const float*)d_in[0];
    const float* trans = (const float*)d_in[1];
    float* out = (float*)d_out;

    const int B = out_size / 64;               // 256
    const int T = in_sizes[0] / (B * 64);      // 512

    const int blocks = (B + 1) / 2;            // 2 batches per 256-thread CTA
    crf_forward_kernel<<<blocks, 256>>>(X, trans, out, B, T);
}

// round 4
// speedup vs baseline: 1.3874x; 1.3874x over previous
#include <cuda_runtime.h>

// CRF forward recursion — fully multiplicative exp2-domain form.
// One WARP per batch (no cross-warp barriers): each lane owns columns
// (2*lane, 2*lane+1), does the full 64-long prev reduction with packed
// fp32x2 FMAs (E matrix resident in registers), p = exp2(alpha - m)
// exchanged via warp-private smem + __syncwarp. Both MUFU ops (lg2/ex2)
// are off the critical path: per step  p' = S * u,  where
// u = exp2(x*log2e - d) is prepared during the previous matvec and
// d = lg2(p[2]) recentres the scale. alpha is reconstructed only at the end.

#define FULLMASK 0xffffffffu
typedef unsigned long long ull;

__device__ __forceinline__ float ex2f_(float x){float r;asm("ex2.approx.f32 %0,%1;":"=f"(r):"f"(x));return r;}
__device__ __forceinline__ float lg2f_(float x){float r;asm("lg2.approx.f32 %0,%1;":"=f"(r):"f"(x));return r;}
__device__ __forceinline__ ull  pack2_(float lo,float hi){ull r;asm("mov.b64 %0,{%1,%2};":"=l"(r):"f"(lo),"f"(hi));return r;}
__device__ __forceinline__ void unpack2_(ull v,float&a,float&b){asm("mov.b64 {%0,%1},%2;":"=f"(a),"=f"(b):"l"(v));}
__device__ __forceinline__ float lo2_(ull v){float a,b;unpack2_(v,a,b);return a;}
__device__ __forceinline__ ull ffma2_(ull a,ull b,ull c){ull d;asm("fma.rn.f32x2 %0,%1,%2,%3;":"=l"(d):"l"(a),"l"(b),"l"(c));return d;}
__device__ __forceinline__ ull fadd2_(ull a,ull b){ull d;asm("add.rn.f32x2 %0,%1,%2;":"=l"(d):"l"(a),"l"(b));return d;}
__device__ __forceinline__ ull fmul2_(ull a,ull b){ull d;asm("mul.rn.f32x2 %0,%1,%2;":"=l"(d):"l"(a),"l"(b));return d;}

__global__ __launch_bounds__(64, 1)
void crf_forward_kernel(const float* __restrict__ X,
                        const float* __restrict__ trans,
                        float* __restrict__ out,
                        int B, int T)
{
    constexpr float LOG2E = 1.4426950408889634f;
    constexpr float LN2   = 0.6931471805599453f;
    constexpr float NEG2  = -10000.0f * 1.4426950408889634f;

    const int tid  = threadIdx.x;
    const int w    = tid >> 5;          // batch slot in CTA (0/1)
    const int lane = tid & 31;
    const int c0   = 2 * lane;          // owned column pair
    const int c1   = c0 + 1;
    int b = blockIdx.x * 2 + w;
    if (b >= B) b = 0;                  // defensive (benign duplicate)

    // p exchange: [warp][double-buffer][prev tag]
    __shared__ __align__(16) float pbuf[2][2][64];

    // ---- E2 = exp2(trans * log2e), packed over prev pairs, in registers.
    // e0[k] = (E[2k][c0], E[2k+1][c0]); e1 same for c1.
    // Column 0 (tag 'B', masked -1e4) overridden to 1.0: S[0] then equals
    // sum(p) and the -1e4 is reapplied exactly in u[0]=0 / the epilogue.
    // Row 1 (tag 'E') underflows to exactly 0 — matches reference.
    ull e0[32], e1[32];
#pragma unroll
    for (int k = 0; k < 32; k++) {
        const float t00 = __ldg(&trans[(2*k    ) * 64 + c0]);
        const float t10 = __ldg(&trans[(2*k + 1) * 64 + c0]);
        const float t01 = __ldg(&trans[(2*k    ) * 64 + c1]);
        const float t11 = __ldg(&trans[(2*k + 1) * 64 + c1]);
        const float f00 = (c0 == 0) ? 1.0f : ex2f_(t00 * LOG2E);
        const float f10 = (c0 == 0) ? 1.0f : ex2f_(t10 * LOG2E);
        e0[k] = pack2_(f00, f10);
        e1[k] = pack2_(ex2f_(t01 * LOG2E), ex2f_(t11 * LOG2E));
    }

    // ---- init p_0 = (1, 0, ..., 0)
    *(ull*)&pbuf[w][0][c0] = pack2_((c0 == 0) ? 1.0f : 0.0f, 0.0f);
    __syncwarp();

    const float* __restrict__ xb = X + (size_t)b * T * 64 + c0;

    // u_0 (d_0 = 0), masked at column 0
    float2 xv = *(const float2*)xb;                       // x_0
    float u0  = (c0 == 0) ? 0.0f : ex2f_(xv.x * LOG2E);
    float u1  = ex2f_(xv.y * LOG2E);
    ull   u   = pack2_(u0, u1);

    float2 xc = (T > 1) ? *(const float2*)(xb + 64) : xv; // x_1
    float M  = 0.0f;   // accumulated shift embedded in p
    float du = 0.0f;   // shift carried by the current u

    int cur = 0;

    for (int t = 0; t < T - 1; t++) {
        const ulonglong2* __restrict__ pp = (const ulonglong2*)pbuf[w][cur];

        // ---- matvec: S[c] = sum_prev p[prev] * E2[prev][c]
        ull a0[4] = {0,0,0,0};
        ull a1[4] = {0,0,0,0};
#pragma unroll
        for (int k = 0; k < 16; k++) {
            const ulonglong2 pv = pp[k];          // prevs 4k..4k+3 (2 packed pairs)
            const int i0 = (k & 1) << 1;
            a0[i0]     = ffma2_(pv.x, e0[2*k],     a0[i0]);
            a0[i0 + 1] = ffma2_(pv.y, e0[2*k + 1], a0[i0 + 1]);
            a1[i0]     = ffma2_(pv.x, e1[2*k],     a1[i0]);
            a1[i0 + 1] = ffma2_(pv.y, e1[2*k + 1], a1[i0 + 1]);
        }
        const ull s0p = fadd2_(fadd2_(a0[0], a0[1]), fadd2_(a0[2], a0[3]));
        const ull s1p = fadd2_(fadd2_(a1[0], a1[1]), fadd2_(a1[2], a1[3]));
        float s0a, s0b, s1a, s1b;
        unpack2_(s0p, s0a, s0b);
        unpack2_(s1p, s1a, s1b);
        const float S0 = s0a + s0b;
        const float S1 = s1a + s1b;

        // ---- scale & store new p (critical path ends here)
        const ull pn = fmul2_(pack2_(S0, S1), u);
        *(ull*)&pbuf[w][cur ^ 1][c0] = pn;

        // ---- off-path: next shift d' = lg2(p'[2]) and next u
        const float p2 = __shfl_sync(FULLMASK, lo2_(pn), 1);  // lane1 holds col 2
        const float dn = lg2f_(p2);
        M += du;
        du = dn;

        const float2 xnext = xc;                   // x_{t+1} -> u_{t+1}
        int t2 = t + 2; if (t2 > T - 1) t2 = T - 1;
        xc = *(const float2*)(xb + (size_t)t2 * 64);

        float un0 = ex2f_(fmaf(xnext.x, LOG2E, -dn));
        float un1 = ex2f_(fmaf(xnext.y, LOG2E, -dn));
        if (c0 == 0) un0 = 0.0f;
        u = pack2_(un0, un1);

        __syncwarp();
        cur ^= 1;
    }

    // ---- epilogue: final matvec, reconstruct alpha in natural log.
    {
        const ulonglong2* __restrict__ pp = (const ulonglong2*)pbuf[w][cur];
        ull a0[4] = {0,0,0,0};
        ull a1[4] = {0,0,0,0};
#pragma unroll
        for (int k = 0; k < 16; k++) {
            const ulonglong2 pv = pp[k];
            const int i0 = (k & 1) << 1;
            a0[i0]     = ffma2_(pv.x, e0[2*k],     a0[i0]);
            a0[i0 + 1] = ffma2_(pv.y, e0[2*k + 1], a0[i0 + 1]);
            a1[i0]     = ffma2_(pv.x, e1[2*k],     a1[i0]);
            a1[i0 + 1] = ffma2_(pv.y, e1[2*k + 1], a1[i0 + 1]);
        }
        const ull s0p = fadd2_(fadd2_(a0[0], a0[1]), fadd2_(a0[2], a0[3]));
        const ull s1p = fadd2_(fadd2_(a1[0], a1[1]), fadd2_(a1[2], a1[3]));
        float s0a, s0b, s1a, s1b;
        unpack2_(s0p, s0a, s0b);
        unpack2_(s1p, s1a, s1b);
        const float S0 = s0a + s0b;
        const float S1 = s1a + s1b;

        // xc == x_{T-1} here (clamped prefetch); M = sum of applied shifts.
        const float mask0 = (c0 == 0) ? NEG2 : 0.0f;
        const float o0 = (lg2f_(S0) + xc.x * LOG2E + mask0 + M) * LN2;
        const float o1 = (lg2f_(S1) + xc.y * LOG2E +         M) * LN2;
        *(float2*)&out[(size_t)b * 64 + c0] = make_float2(o0, o1);
    }
}

extern "C" void kernel_launch(void* const* d_in, const int* in_sizes, int n_in,
                              void* d_out, int out_size)
{
    const float* X     = (const float*)d_in[0];
    const float* trans = (const float*)d_in[1];
    float* out = (float*)d_out;

    const int B = out_size / 64;               // 256
    const int T = in_sizes[0] / (B * 64);      // 512

    const int blocks = (B + 1) / 2;            // 2 warps per CTA, 1 batch each
    crf_forward_kernel<<<blocks, 64>>>(X, trans, out, B, T);
}